// round 4
// baseline (speedup 1.0000x reference)
#include <cuda_runtime.h>

// Problem constants
#define Bb 4
#define Ss 128
#define Dd 768
#define Hh 768
#define MT (Bb * Ss)     // 512 rows per projection GEMM
#define HPAIRS (Hh / 2)  // 384

// Scratch for projected activations (allocation-free rule: __device__ globals)
__device__ float g_ha[MT * Hh];   // a @ W1[:D] + b1
__device__ float g_hb[MT * Hh];   // b @ W1[D:]

typedef unsigned long long u64;

// ---- packed f32x2 helpers (sm_103a FFMA2 path, only reachable via PTX) ----
static __device__ __forceinline__ u64 pk_dup(float x) {
    u64 r; asm("mov.b64 %0, {%1, %1};" : "=l"(r) : "f"(x)); return r;
}
static __device__ __forceinline__ u64 pk2(float lo, float hi) {
    u64 r; asm("mov.b64 %0, {%1, %2};" : "=l"(r) : "f"(lo), "f"(hi)); return r;
}
static __device__ __forceinline__ void fma2(u64& d, u64 a, u64 b) {
    asm("fma.rn.f32x2 %0, %1, %2, %0;" : "+l"(d) : "l"(a), "l"(b));
}
static __device__ __forceinline__ void upk(u64 v, float& lo, float& hi) {
    asm("mov.b64 {%0, %1}, %2;" : "=f"(lo), "=f"(hi) : "l"(v));
}

// ============================================================================
// Stage 1: ha = a @ W1[:768] + b1 ; hb = b @ W1[768:]
// BM=64 BN=32 BK=16, 256 threads, TM=4(2 packed M-pairs) x TN=2 per thread.
// MOV-free inner loop: A tile stored k-major (ulonglong2 read = 2 packed
// M-pair operands), W tile stored PRE-DUPLICATED as u64 (dup paid once at
// staging). Inner kk: 2 LDS.128 + 4 FFMA2. Double-buffered smem: 1 sync/blk.
// grid = (8, 24, 2) = 384 CTAs (2-3 resident per SM; fma-pipe bound)
// ============================================================================
#define BM 64
#define BN 32
#define BK 16
#define PA 68   // padded pitch for k-major A tile (68*4 bytes, 16B-aligned rows)
#define NKB (Dd / BK)   // 48 k-blocks

__global__ __launch_bounds__(256) void proj_kernel(
    const float* __restrict__ a, const float* __restrict__ b,
    const float* __restrict__ W1, const float* __restrict__ b1)
{
    __shared__ float As[2][BK][PA];   // As[buf][k][m]
    __shared__ u64   Wsd[2][BK][BN];  // duplicated W: (w,w) packed

    const int z = blockIdx.z;
    const float* __restrict__ X  = z ? b : a;
    const float* __restrict__ Wg = W1 + (size_t)z * Dd * Hh;
    float* __restrict__ Cg       = z ? g_hb : g_ha;

    const int tid    = threadIdx.x;
    const int m_tile = blockIdx.x * BM;
    const int n_tile = blockIdx.y * BN;

    // global-load mapping
    const int lm  = tid >> 2;          // 0..63  (A row)
    const int lk4 = (tid & 3) << 2;    // 0,4,8,12 (A k-offset, float4)
    const int wk  = tid >> 4;          // 0..15  (W k-row)
    const int wn  = (tid & 15) << 1;   // 0,2,..,30 (W n-offset, float2)

    // compute mapping: 4 rows (2 packed pairs) x 2 cols per thread
    const int n0 = (tid & 15) << 1;
    const int m0 = (tid >> 4) << 2;

    const float* Xp = X  + (size_t)(m_tile + lm) * Dd + lk4;
    const float* Wp = Wg + (size_t)wk * Hh + n_tile + wn;

    u64 acc00 = 0, acc01 = 0, acc10 = 0, acc11 = 0;  // acc[mpair][n]

    // stage k-block 0 into buffer 0
    {
        float4 av0 = *reinterpret_cast<const float4*>(Xp);
        float2 wv0 = *reinterpret_cast<const float2*>(Wp);
        As[0][lk4 + 0][lm] = av0.x;
        As[0][lk4 + 1][lm] = av0.y;
        As[0][lk4 + 2][lm] = av0.z;
        As[0][lk4 + 3][lm] = av0.w;
        Wsd[0][wk][wn]     = pk_dup(wv0.x);
        Wsd[0][wk][wn + 1] = pk_dup(wv0.y);
    }
    __syncthreads();

    float4 av; float2 wv;
    for (int kb = 0; kb < NKB; kb++) {
        const int cur = kb & 1;
        if (kb + 1 < NKB) {   // prefetch next block into registers
            av = *reinterpret_cast<const float4*>(Xp + (kb + 1) * BK);
            wv = *reinterpret_cast<const float2*>(Wp + (size_t)(kb + 1) * BK * Hh);
        }
        #pragma unroll
        for (int kk = 0; kk < BK; kk++) {
            ulonglong2 ap = *reinterpret_cast<const ulonglong2*>(&As[cur][kk][m0]);
            ulonglong2 wd = *reinterpret_cast<const ulonglong2*>(&Wsd[cur][kk][n0]);
            fma2(acc00, ap.x, wd.x);
            fma2(acc01, ap.x, wd.y);
            fma2(acc10, ap.y, wd.x);
            fma2(acc11, ap.y, wd.y);
        }
        if (kb + 1 < NKB) {   // store prefetched block into the other buffer
            const int nxt = cur ^ 1;
            As[nxt][lk4 + 0][lm] = av.x;
            As[nxt][lk4 + 1][lm] = av.y;
            As[nxt][lk4 + 2][lm] = av.z;
            As[nxt][lk4 + 3][lm] = av.w;
            Wsd[nxt][wk][wn]     = pk_dup(wv.x);
            Wsd[nxt][wk][wn + 1] = pk_dup(wv.y);
        }
        __syncthreads();
    }

    float c00l, c00h, c01l, c01h, c10l, c10h, c11l, c11h;
    upk(acc00, c00l, c00h);
    upk(acc01, c01l, c01h);
    upk(acc10, c10l, c10h);
    upk(acc11, c11l, c11h);

    float bias0 = 0.f, bias1 = 0.f;
    if (z == 0) { bias0 = b1[n_tile + n0]; bias1 = b1[n_tile + n0 + 1]; }

    float* Cp = Cg + (size_t)(m_tile + m0) * Hh + n_tile + n0;
    *reinterpret_cast<float2*>(Cp         ) = make_float2(c00l + bias0, c01l + bias1);
    *reinterpret_cast<float2*>(Cp +     Hh) = make_float2(c00h + bias0, c01h + bias1);
    *reinterpret_cast<float2*>(Cp + 2 * Hh) = make_float2(c10l + bias0, c11l + bias1);
    *reinterpret_cast<float2*>(Cp + 3 * Hh) = make_float2(c10h + bias0, c11h + bias1);
}

// ============================================================================
// Stage 2: out[b,i,j,:] = relu(ha[b,i,:] + hb[b,j,:]) @ W2 + b2
// CTA = 16 i x 16 j, 256 threads, one pair per thread, h streamed in 128-chunks.
// o-major FFMA2: acc_o accumulates (even-h, odd-h) partials against W2
// pre-packed in smem as (W2[2h,o], W2[2h+1,o]) — NO per-h dup MOVs.
// Per 4h: 4 LDS + 4 FADD + 4 FMNMX + 2 pk2 + 4 FFMA2.
// grid = (8, 8, 4) = 256 CTAs -> most SMs host 2 CTAs (occupancy fix).
// ============================================================================
#define TI 16
#define TJ 16
#define HC 128
#define PP 132  // padded pitch: conflict-free LDS.128 across 16 rows per phase

__global__ __launch_bounds__(256) void pair_kernel(
    const float* __restrict__ W2, const float* __restrict__ b2,
    float2* __restrict__ out)
{
    __shared__ float sha[TI][PP];
    __shared__ float shb[TJ][PP];
    __shared__ u64   swp[2][HPAIRS];  // swp[o][hp] = (W2[2hp,o], W2[2hp+1,o])

    const int tid = threadIdx.x;
    const int bi = blockIdx.x, bj = blockIdx.y, bb = blockIdx.z;

    const int li = tid >> 4;   // 0..15 : i within tile
    const int lj = tid & 15;   // 0..15 : j within tile

    const float* haBase = g_ha + (size_t)(bb * Ss + bi * TI) * Hh;
    const float* hbBase = g_hb + (size_t)(bb * Ss + bj * TJ) * Hh;

    // stage ALL of W2 once, o-major packed (384 h-pairs x 2 outputs)
    for (int hp = tid; hp < HPAIRS; hp += 256) {
        float4 w = *reinterpret_cast<const float4*>(W2 + 4 * hp);
        swp[0][hp] = pk2(w.x, w.z);   // o=0: (W2[2hp,0], W2[2hp+1,0])
        swp[1][hp] = pk2(w.y, w.w);   // o=1
    }

    // 4 accumulator chains (even/odd h-pair interleave) to cover FFMA2 latency
    u64 acc0e = 0, acc0o = 0, acc1e = 0, acc1o = 0;

    // prefetch chunk 0 (16 rows x 128 floats = 512 float4 per tile; 2/thread)
    float4 va[2], vb[2];
    {
        #pragma unroll
        for (int r = 0; r < 2; r++) {
            int idx = r * 256 + tid;
            va[r] = *reinterpret_cast<const float4*>(
                haBase + (size_t)(idx >> 5) * Hh + ((idx & 31) << 2));
            vb[r] = *reinterpret_cast<const float4*>(
                hbBase + (size_t)(idx >> 5) * Hh + ((idx & 31) << 2));
        }
    }

    for (int h0 = 0; h0 < Hh; h0 += HC) {
        __syncthreads();
        #pragma unroll
        for (int r = 0; r < 2; r++) {
            int idx = r * 256 + tid;
            *reinterpret_cast<float4*>(&sha[idx >> 5][(idx & 31) << 2]) = va[r];
            *reinterpret_cast<float4*>(&shb[idx >> 5][(idx & 31) << 2]) = vb[r];
        }
        __syncthreads();

        if (h0 + HC < Hh) {   // prefetch next chunk under compute
            int hn = h0 + HC;
            #pragma unroll
            for (int r = 0; r < 2; r++) {
                int idx = r * 256 + tid;
                va[r] = *reinterpret_cast<const float4*>(
                    haBase + (size_t)(idx >> 5) * Hh + hn + ((idx & 31) << 2));
                vb[r] = *reinterpret_cast<const float4*>(
                    hbBase + (size_t)(idx >> 5) * Hh + hn + ((idx & 31) << 2));
            }
        }

        const int hpBase = h0 >> 1;
        #pragma unroll 8
        for (int c = 0; c < HC; c += 4) {
            float4 xa = *reinterpret_cast<const float4*>(&sha[li][c]);
            float4 xb = *reinterpret_cast<const float4*>(&shb[lj][c]);
            ulonglong2 w0 = *reinterpret_cast<const ulonglong2*>(&swp[0][hpBase + (c >> 1)]);
            ulonglong2 w1 = *reinterpret_cast<const ulonglong2*>(&swp[1][hpBase + (c >> 1)]);
            float s0 = fmaxf(xa.x + xb.x, 0.f);
            float s1 = fmaxf(xa.y + xb.y, 0.f);
            float s2 = fmaxf(xa.z + xb.z, 0.f);
            float s3 = fmaxf(xa.w + xb.w, 0.f);
            u64 sp0 = pk2(s0, s1);
            u64 sp1 = pk2(s2, s3);
            fma2(acc0e, sp0, w0.x);
            fma2(acc1e, sp0, w1.x);
            fma2(acc0o, sp1, w0.y);
            fma2(acc1o, sp1, w1.y);
        }
    }

    float a0, a1, a2, a3, a4, a5, a6, a7;
    upk(acc0e, a0, a1); upk(acc0o, a2, a3);
    upk(acc1e, a4, a5); upk(acc1o, a6, a7);
    const float o0 = a0 + a1 + a2 + a3 + b2[0];
    const float o1 = a4 + a5 + a6 + a7 + b2[1];

    size_t base = ((size_t)bb * Ss + bi * TI + li) * Ss + bj * TJ + lj;
    out[base] = make_float2(o0, o1);
}

// ============================================================================
// launch
// ============================================================================
extern "C" void kernel_launch(void* const* d_in, const int* in_sizes, int n_in,
                              void* d_out, int out_size)
{
    // Input mapping by element count:
    // a,b: 393216 ; W1: 1179648 ; b1: 768 ; W2: 1536 ; b2: 2
    const float *a = nullptr, *b = nullptr, *W1 = nullptr, *b1 = nullptr,
                *W2 = nullptr, *b2 = nullptr;
    for (int i = 0; i < n_in; i++) {
        const float* p = (const float*)d_in[i];
        switch (in_sizes[i]) {
            case MT * Dd:      if (!a) a = p; else b = p; break;  // a first, then b
            case 2 * Dd * Hh:  W1 = p; break;
            case Hh:           b1 = p; break;
            case Hh * 2:       W2 = p; break;
            case 2:            b2 = p; break;
            default: break;
        }
    }

    dim3 g1(MT / BM, Hh / BN, 2);        // (8, 24, 2) = 384 CTAs
    proj_kernel<<<g1, 256>>>(a, b, W1, b1);

    dim3 g2(Ss / TI, Ss / TJ, Bb);       // (8, 8, 4) = 256 CTAs
    pair_kernel<<<g2, 256>>>(W2, b2, (float2*)d_out);

    (void)out_size;
}

// round 7
// speedup vs baseline: 1.2247x; 1.2247x over previous
#include <cuda_runtime.h>
#include <cuda_bf16.h>
#include <mma.h>
#include <cstdint>

using namespace nvcuda;

// Problem constants
#define Bb 4
#define Ss 128
#define Dd 768
#define Hh 768
#define MT (Bb * Ss)     // 512 rows per projection GEMM
#define KP 2304          // split-concat K: [hi | lo | hi] x [Whi | Whi | Wlo]

// ---------------------------------------------------------------------------
// Device scratch (allocation-free rule: __device__ globals)
// ---------------------------------------------------------------------------
__device__ float g_ha[MT * Hh];   // a @ W1[:D] + b1
__device__ float g_hb[MT * Hh];   // b @ W1[D:]

// split-concat bf16 operands
__device__ __align__(16) __nv_bfloat16 g_xs[2][MT * KP];   // [z][m][k']
__device__ __align__(16) __nv_bfloat16 g_ws[2][Hh * KP];   // [z][h][k']

typedef unsigned long long u64;

// packed f32x2 helpers (pair kernel)
static __device__ __forceinline__ u64 pk_dup(float x) {
    u64 r; asm("mov.b64 %0, {%1, %1};" : "=l"(r) : "f"(x)); return r;
}
static __device__ __forceinline__ void fma2(u64& d, u64 a, u64 b) {
    asm("fma.rn.f32x2 %0, %1, %2, %0;" : "+l"(d) : "l"(a), "l"(b));
}
static __device__ __forceinline__ void upk(u64 v, float& lo, float& hi) {
    asm("mov.b64 {%0, %1}, %2;" : "=f"(lo), "=f"(hi) : "l"(v));
}

// ---------------------------------------------------------------------------
// conv_x: split a/b (fp32) into concat layout [hi | lo | hi].
// grid (384, 2), 256 thr; each thread handles 4 consecutive k of one row.
// ---------------------------------------------------------------------------
__global__ __launch_bounds__(256) void conv_x(
    const float* __restrict__ a, const float* __restrict__ b)
{
    const int z = blockIdx.y;
    const float* __restrict__ X = z ? b : a;
    __nv_bfloat16* __restrict__ dst = g_xs[z];

    int i4 = (blockIdx.x * 256 + threadIdx.x) * 4;
    int m = i4 / Dd, k = i4 % Dd;
    float4 v = *reinterpret_cast<const float4*>(X + i4);
    __nv_bfloat16 h0 = __float2bfloat16(v.x), h1 = __float2bfloat16(v.y);
    __nv_bfloat16 h2 = __float2bfloat16(v.z), h3 = __float2bfloat16(v.w);
    __nv_bfloat16 l0 = __float2bfloat16(v.x - __bfloat162float(h0));
    __nv_bfloat16 l1 = __float2bfloat16(v.y - __bfloat162float(h1));
    __nv_bfloat16 l2 = __float2bfloat16(v.z - __bfloat162float(h2));
    __nv_bfloat16 l3 = __float2bfloat16(v.w - __bfloat162float(h3));

    size_t base = (size_t)m * KP + k;
    __nv_bfloat162 hp0(h0, h1), hp1(h2, h3), lp0(l0, l1), lp1(l2, l3);
    __nv_bfloat162* p;
    p = reinterpret_cast<__nv_bfloat162*>(dst + base);            p[0] = hp0; p[1] = hp1;
    p = reinterpret_cast<__nv_bfloat162*>(dst + base + Dd);       p[0] = lp0; p[1] = lp1;
    p = reinterpret_cast<__nv_bfloat162*>(dst + base + 2 * Dd);   p[0] = hp0; p[1] = hp1;
}

// ---------------------------------------------------------------------------
// conv_w: transpose W1 [1536, 768] -> ws[z][h][k'] = [Whi | Whi | Wlo]
// grid (24, 48), 256 thr, 32x32 smem tile transpose
// ---------------------------------------------------------------------------
__global__ __launch_bounds__(256) void conv_w(const float* __restrict__ W1)
{
    __shared__ float t[32][33];
    const int tx = threadIdx.x & 31, ty = threadIdx.x >> 5;
    const int h0 = blockIdx.x * 32, dg0 = blockIdx.y * 32;

    #pragma unroll
    for (int r = 0; r < 4; r++) {
        int rd = ty + 8 * r;
        t[rd][tx] = W1[(size_t)(dg0 + rd) * Hh + h0 + tx];
    }
    __syncthreads();

    const int z = dg0 / Dd;
    const int d0 = dg0 % Dd;
    __nv_bfloat16* __restrict__ dst = g_ws[z];
    #pragma unroll
    for (int r = 0; r < 4; r++) {
        int rh = ty + 8 * r;
        float v = t[tx][rh];                     // = W1[dg0+tx][h0+rh]
        __nv_bfloat16 hv = __float2bfloat16(v);
        __nv_bfloat16 lv = __float2bfloat16(v - __bfloat162float(hv));
        size_t base = (size_t)(h0 + rh) * KP + d0 + tx;
        dst[base]          = hv;   // term: hi * Whi
        dst[base + Dd]     = hv;   // term: lo * Whi
        dst[base + 2 * Dd] = lv;   // term: hi * Wlo
    }
}

// ---------------------------------------------------------------------------
// gemm_kernel: h[z] = X'[z] @ W'[z]^T (+ b1 for z=0) via wmma bf16 HMMA
// BM=128, BN=64, BK=32, K'=2304. 8 warps in 4x2, warp tile 32x32 (2x2 wmma
// m16n16k16). Double-buffered smem + register prefetch. Epilogue staged
// through smem (union with tiles) for coalesced biased fp32 writes.
// grid (4, 12, 2) = 96 CTAs, 256 threads.
// ---------------------------------------------------------------------------
#define GBM 128
#define GBN 64
#define GBK 32
#define LDT 40            // bf16 tile pitch (pad 8)
#define LDC 68            // fp32 epilogue pitch (pad 4)
#define NKB (KP / GBK)    // 72

#define TILES_BYTES (2 * GBM * LDT * 2 + 2 * GBN * LDT * 2)  // 30720
#define CS_BYTES    (GBM * LDC * 4)                          // 34816

__global__ __launch_bounds__(256) void gemm_kernel(const float* __restrict__ b1)
{
    __shared__ __align__(16) char sm[CS_BYTES + 256];
    // union layout: A tiles [0, 20480), B tiles [20480, 30720) | Cs [0, 34816)
    __nv_bfloat16 (*As)[GBM][LDT] =
        reinterpret_cast<__nv_bfloat16(*)[GBM][LDT]>(sm);
    __nv_bfloat16 (*Bs)[GBN][LDT] =
        reinterpret_cast<__nv_bfloat16(*)[GBN][LDT]>(sm + 2 * GBM * LDT * 2);
    float (*Cs)[LDC] = reinterpret_cast<float(*)[LDC]>(sm);
    float* bias = reinterpret_cast<float*>(sm + CS_BYTES);

    const int tid = threadIdx.x;
    const int wid = tid >> 5;
    const int wm = wid & 3;           // 0..3 : M warp coord
    const int wn = wid >> 2;          // 0..1 : N warp coord
    const int m_tile = blockIdx.x * GBM;
    const int n_tile = blockIdx.y * GBN;
    const int z = blockIdx.z;

    const __nv_bfloat16* __restrict__ X = g_xs[z];
    const __nv_bfloat16* __restrict__ W = g_ws[z];
    float* __restrict__ Cg = z ? g_hb : g_ha;

    if (tid < GBN)
        bias[tid] = z ? 0.f : b1[n_tile + tid];

    // global-load mapping (uint4 = 8 bf16)
    const int ar0 = tid >> 2;              // A row for idx=tid       (0..63)
    const int ar1 = (tid + 256) >> 2;      // A row for idx=tid+256   (64..127)
    const int ac  = (tid & 3) * 8;         // k offset within block
    const int br  = tid >> 2;              // B row (0..63)

    const __nv_bfloat16* Xp0 = X + (size_t)(m_tile + ar0) * KP + ac;
    const __nv_bfloat16* Xp1 = X + (size_t)(m_tile + ar1) * KP + ac;
    const __nv_bfloat16* Wp  = W + (size_t)(n_tile + br)  * KP + ac;

    // stage k-block 0
    {
        uint4 a0 = *reinterpret_cast<const uint4*>(Xp0);
        uint4 a1 = *reinterpret_cast<const uint4*>(Xp1);
        uint4 b0 = *reinterpret_cast<const uint4*>(Wp);
        *reinterpret_cast<uint4*>(&As[0][ar0][ac]) = a0;
        *reinterpret_cast<uint4*>(&As[0][ar1][ac]) = a1;
        *reinterpret_cast<uint4*>(&Bs[0][br][ac])  = b0;
    }
    __syncthreads();

    wmma::fragment<wmma::accumulator, 16, 16, 16, float> acc[2][2];
    #pragma unroll
    for (int i = 0; i < 2; i++)
        #pragma unroll
        for (int j = 0; j < 2; j++)
            wmma::fill_fragment(acc[i][j], 0.f);

    uint4 ra0, ra1, rb0;
    for (int kb = 0; kb < NKB; kb++) {
        const int cur = kb & 1;
        if (kb + 1 < NKB) {
            ra0 = *reinterpret_cast<const uint4*>(Xp0 + (kb + 1) * GBK);
            ra1 = *reinterpret_cast<const uint4*>(Xp1 + (kb + 1) * GBK);
            rb0 = *reinterpret_cast<const uint4*>(Wp  + (kb + 1) * GBK);
        }

        #pragma unroll
        for (int ks = 0; ks < GBK; ks += 16) {
            wmma::fragment<wmma::matrix_a, 16, 16, 16, __nv_bfloat16,
                           wmma::row_major> af[2];
            wmma::fragment<wmma::matrix_b, 16, 16, 16, __nv_bfloat16,
                           wmma::col_major> bf[2];
            #pragma unroll
            for (int i = 0; i < 2; i++)
                wmma::load_matrix_sync(af[i], &As[cur][wm * 32 + 16 * i][ks], LDT);
            #pragma unroll
            for (int j = 0; j < 2; j++)
                wmma::load_matrix_sync(bf[j], &Bs[cur][wn * 32 + 16 * j][ks], LDT);
            #pragma unroll
            for (int i = 0; i < 2; i++)
                #pragma unroll
                for (int j = 0; j < 2; j++)
                    wmma::mma_sync(acc[i][j], af[i], bf[j], acc[i][j]);
        }

        if (kb + 1 < NKB) {
            const int nxt = cur ^ 1;
            *reinterpret_cast<uint4*>(&As[nxt][ar0][ac]) = ra0;
            *reinterpret_cast<uint4*>(&As[nxt][ar1][ac]) = ra1;
            *reinterpret_cast<uint4*>(&Bs[nxt][br][ac])  = rb0;
        }
        __syncthreads();
    }

    // epilogue: stage C through smem (aliases tiles; loop ended with sync)
    #pragma unroll
    for (int i = 0; i < 2; i++)
        #pragma unroll
        for (int j = 0; j < 2; j++)
            wmma::store_matrix_sync(&Cs[wm * 32 + 16 * i][wn * 32 + 16 * j],
                                    acc[i][j], LDC, wmma::mem_row_major);
    __syncthreads();

    // biased coalesced write: 128 rows x 16 float4
    for (int t = tid; t < GBM * (GBN / 4); t += 256) {
        int r  = t >> 4;
        int c4 = (t & 15) * 4;
        float4 v = *reinterpret_cast<const float4*>(&Cs[r][c4]);
        v.x += bias[c4];
        v.y += bias[c4 + 1];
        v.z += bias[c4 + 2];
        v.w += bias[c4 + 3];
        *reinterpret_cast<float4*>(
            Cg + (size_t)(m_tile + r) * Hh + n_tile + c4) = v;
    }
}

// ---------------------------------------------------------------------------
// pair_kernel — UNCHANGED known-good 18.4us version:
// out[b,i,j,:] = relu(ha[b,i,:] + hb[b,j,:]) @ W2 + b2
// ---------------------------------------------------------------------------
#define TI 16
#define TJ 32
#define HC 128
#define PP 132

__global__ __launch_bounds__(256) void pair_kernel(
    const float* __restrict__ W2, const float* __restrict__ b2,
    float2* __restrict__ out)
{
    __shared__ float sha[TI][PP];
    __shared__ float shb[TJ][PP];
    __shared__ u64   sw2[HC];      // packed (W2[h,0], W2[h,1])

    const int tid = threadIdx.x;
    const int bi = blockIdx.x, bj = blockIdx.y, bb = blockIdx.z;

    const int li = tid >> 4;   // 0..15 : i within tile
    const int lj = tid & 15;   // j and j+16 within tile

    const float* haBase = g_ha + (size_t)(bb * Ss + bi * TI) * Hh;
    const float* hbBase = g_hb + (size_t)(bb * Ss + bj * TJ) * Hh;

    u64 accA = 0, accB = 0;

    float4 va[2], vb[4], vw;
    {
        #pragma unroll
        for (int r = 0; r < 2; r++) {
            int idx = r * 256 + tid;
            va[r] = *reinterpret_cast<const float4*>(
                haBase + (size_t)(idx >> 5) * Hh + ((idx & 31) << 2));
        }
        #pragma unroll
        for (int r = 0; r < 4; r++) {
            int idx = r * 256 + tid;
            vb[r] = *reinterpret_cast<const float4*>(
                hbBase + (size_t)(idx >> 5) * Hh + ((idx & 31) << 2));
        }
        if (tid < 64) vw = *reinterpret_cast<const float4*>(W2 + tid * 4);
    }

    for (int h0 = 0; h0 < Hh; h0 += HC) {
        __syncthreads();
        #pragma unroll
        for (int r = 0; r < 2; r++) {
            int idx = r * 256 + tid;
            *reinterpret_cast<float4*>(&sha[idx >> 5][(idx & 31) << 2]) = va[r];
        }
        #pragma unroll
        for (int r = 0; r < 4; r++) {
            int idx = r * 256 + tid;
            *reinterpret_cast<float4*>(&shb[idx >> 5][(idx & 31) << 2]) = vb[r];
        }
        if (tid < 64) *reinterpret_cast<float4*>(&sw2[tid * 2]) = vw;
        __syncthreads();

        if (h0 + HC < Hh) {
            int hn = h0 + HC;
            #pragma unroll
            for (int r = 0; r < 2; r++) {
                int idx = r * 256 + tid;
                va[r] = *reinterpret_cast<const float4*>(
                    haBase + (size_t)(idx >> 5) * Hh + hn + ((idx & 31) << 2));
            }
            #pragma unroll
            for (int r = 0; r < 4; r++) {
                int idx = r * 256 + tid;
                vb[r] = *reinterpret_cast<const float4*>(
                    hbBase + (size_t)(idx >> 5) * Hh + hn + ((idx & 31) << 2));
            }
            if (tid < 64) vw = *reinterpret_cast<const float4*>(W2 + 2 * hn + tid * 4);
        }

        #pragma unroll 8
        for (int c = 0; c < HC; c += 4) {
            float4 xa  = *reinterpret_cast<const float4*>(&sha[li][c]);
            float4 xb0 = *reinterpret_cast<const float4*>(&shb[lj][c]);
            float4 xb1 = *reinterpret_cast<const float4*>(&shb[lj + 16][c]);
            u64 w0 = sw2[c], w1 = sw2[c + 1], w2v = sw2[c + 2], w3 = sw2[c + 3];
            float sA, sB;
            sA = fmaxf(xa.x + xb0.x, 0.f); sB = fmaxf(xa.x + xb1.x, 0.f);
            fma2(accA, pk_dup(sA), w0);    fma2(accB, pk_dup(sB), w0);
            sA = fmaxf(xa.y + xb0.y, 0.f); sB = fmaxf(xa.y + xb1.y, 0.f);
            fma2(accA, pk_dup(sA), w1);    fma2(accB, pk_dup(sB), w1);
            sA = fmaxf(xa.z + xb0.z, 0.f); sB = fmaxf(xa.z + xb1.z, 0.f);
            fma2(accA, pk_dup(sA), w2v);   fma2(accB, pk_dup(sB), w2v);
            sA = fmaxf(xa.w + xb0.w, 0.f); sB = fmaxf(xa.w + xb1.w, 0.f);
            fma2(accA, pk_dup(sA), w3);    fma2(accB, pk_dup(sB), w3);
        }
    }

    float aAl, aAh, aBl, aBh;
    upk(accA, aAl, aAh);
    upk(accB, aBl, aBh);
    const float b20 = b2[0], b21 = b2[1];

    size_t base = ((size_t)bb * Ss + bi * TI + li) * Ss + bj * TJ + lj;
    out[base]      = make_float2(aAl + b20, aAh + b21);
    out[base + 16] = make_float2(aBl + b20, aBh + b21);
}

// ---------------------------------------------------------------------------
// launch
// ---------------------------------------------------------------------------
extern "C" void kernel_launch(void* const* d_in, const int* in_sizes, int n_in,
                              void* d_out, int out_size)
{
    // Input mapping by element count:
    // a,b: 393216 ; W1: 1179648 ; b1: 768 ; W2: 1536 ; b2: 2
    const float *a = nullptr, *b = nullptr, *W1 = nullptr, *b1 = nullptr,
                *W2 = nullptr, *b2 = nullptr;
    for (int i = 0; i < n_in; i++) {
        const float* p = (const float*)d_in[i];
        switch (in_sizes[i]) {
            case MT * Dd:      if (!a) a = p; else b = p; break;  // a first, then b
            case 2 * Dd * Hh:  W1 = p; break;
            case Hh:           b1 = p; break;
            case Hh * 2:       W2 = p; break;
            case 2:            b2 = p; break;
            default: break;
        }
    }

    conv_x<<<dim3(MT * Dd / 1024, 2), 256>>>(a, b);
    conv_w<<<dim3(Hh / 32, 2 * Dd / 32), 256>>>(W1);
    gemm_kernel<<<dim3(MT / GBM, Hh / GBN, 2), 256>>>(b1);
    pair_kernel<<<dim3(Ss / TI, Ss / TJ, Bb), 256>>>(W2, b2, (float2*)d_out);

    (void)out_size;
}

// round 8
// speedup vs baseline: 1.8328x; 1.4966x over previous
#include <cuda_runtime.h>
#include <cuda_bf16.h>
#include <mma.h>
#include <cstdint>

using namespace nvcuda;

// Problem constants
#define Bb 4
#define Ss 128
#define Dd 768
#define Hh 768
#define MT (Bb * Ss)          // 512 rows per projection GEMM
#define NA (MT * Dd)          // 393216 elements in a (and in b)
#define NW (2 * Dd * Hh)      // 1179648 elements in W1

// ---------------------------------------------------------------------------
// Device scratch (allocation-free rule: __device__ globals)
// ---------------------------------------------------------------------------
__device__ float g_ha[MT * Hh];   // a @ W1[:D] + b1
__device__ float g_hb[MT * Hh];   // b @ W1[D:]

// bf16 split operands, SAME layout as sources (no transpose, no duplication)
__device__ __align__(16) __nv_bfloat16 g_xa_hi[NA], g_xa_lo[NA];   // [m][d]
__device__ __align__(16) __nv_bfloat16 g_xb_hi[NA], g_xb_lo[NA];   // [m][d]
__device__ __align__(16) __nv_bfloat16 g_w_hi[NW],  g_w_lo[NW];    // [d'][h] (d'=z*768+d)

typedef unsigned long long u64;

// packed f32x2 helpers (pair kernel)
static __device__ __forceinline__ u64 pk_dup(float x) {
    u64 r; asm("mov.b64 %0, {%1, %1};" : "=l"(r) : "f"(x)); return r;
}
static __device__ __forceinline__ void fma2(u64& d, u64 a, u64 b) {
    asm("fma.rn.f32x2 %0, %1, %2, %0;" : "+l"(d) : "l"(a), "l"(b));
}
static __device__ __forceinline__ void upk(u64 v, float& lo, float& hi) {
    asm("mov.b64 {%0, %1}, %2;" : "=f"(lo), "=f"(hi) : "l"(v));
}

// ---------------------------------------------------------------------------
// split_kernel: fused fp32 -> (hi, lo) bf16 split for a, b, W1.
// Layout-preserving, fully coalesced. 1920 blocks x 256 thr, 4 elems/thread.
// ---------------------------------------------------------------------------
__global__ __launch_bounds__(256) void split_kernel(
    const float* __restrict__ a, const float* __restrict__ b,
    const float* __restrict__ W1)
{
    int i4 = (blockIdx.x * 256 + threadIdx.x) * 4;
    const float* __restrict__ src;
    __nv_bfloat16 *dhi, *dlo;
    int off;
    if (i4 < NA)            { src = a;  dhi = g_xa_hi; dlo = g_xa_lo; off = i4; }
    else if (i4 < 2 * NA)   { src = b;  dhi = g_xb_hi; dlo = g_xb_lo; off = i4 - NA; }
    else                    { src = W1; dhi = g_w_hi;  dlo = g_w_lo;  off = i4 - 2 * NA; }

    float4 v = *reinterpret_cast<const float4*>(src + off);
    __nv_bfloat16 h0 = __float2bfloat16(v.x), h1 = __float2bfloat16(v.y);
    __nv_bfloat16 h2 = __float2bfloat16(v.z), h3 = __float2bfloat16(v.w);
    __nv_bfloat16 l0 = __float2bfloat16(v.x - __bfloat162float(h0));
    __nv_bfloat16 l1 = __float2bfloat16(v.y - __bfloat162float(h1));
    __nv_bfloat16 l2 = __float2bfloat16(v.z - __bfloat162float(h2));
    __nv_bfloat16 l3 = __float2bfloat16(v.w - __bfloat162float(h3));
    __nv_bfloat162* hp = reinterpret_cast<__nv_bfloat162*>(dhi + off);
    __nv_bfloat162* lp = reinterpret_cast<__nv_bfloat162*>(dlo + off);
    hp[0] = __nv_bfloat162(h0, h1); hp[1] = __nv_bfloat162(h2, h3);
    lp[0] = __nv_bfloat162(l0, l1); lp[1] = __nv_bfloat162(l2, l3);
}

// ---------------------------------------------------------------------------
// gemm_kernel: h[z] = X[z] @ W1[z] (+ b1 for z=0), wmma bf16 HMMA,
// 3 split terms per k-step: hi*Whi + lo*Whi + hi*Wlo (lo*lo dropped ~2^-18).
// BM=128, BN=64, BK=32, 24 k-blocks. 8 warps (4x2), warp tile 32x32
// (2x2 m16n16k16 frags). W1 consumed DIRECTLY in its [k][n] layout as
// row-major matrix_b. Double-buffered smem + register prefetch.
// grid (4, 12, 2) = 96 CTAs, 256 threads, dynamic smem 59.6KB.
// ---------------------------------------------------------------------------
#define GBM 128
#define GBN 64
#define GBK 32
#define LDA 40    // A smem pitch: 32 k + 8 pad (bf16)
#define LDB 72    // B smem pitch: 64 n + 8 pad (bf16)
#define LDC 68    // epilogue fp32 pitch
#define NKB (Dd / GBK)   // 24

#define OFF_AH 0
#define OFF_AL (OFF_AH + 2 * GBM * LDA * 2)   // 20480
#define OFF_BH (OFF_AL + 2 * GBM * LDA * 2)   // 40960
#define OFF_BL (OFF_BH + 2 * GBK * LDB * 2)   // 50176
#define OFF_END (OFF_BL + 2 * GBK * LDB * 2)  // 59392
#define OFF_BIAS OFF_END
#define SM_TOT (OFF_BIAS + 256)               // 59648 (Cs aliases [0, 34816))

__global__ __launch_bounds__(256) void gemm_kernel(const float* __restrict__ b1)
{
    extern __shared__ __align__(16) char sm[];
    __nv_bfloat16 (*AsH)[GBM][LDA] = reinterpret_cast<__nv_bfloat16(*)[GBM][LDA]>(sm + OFF_AH);
    __nv_bfloat16 (*AsL)[GBM][LDA] = reinterpret_cast<__nv_bfloat16(*)[GBM][LDA]>(sm + OFF_AL);
    __nv_bfloat16 (*BsH)[GBK][LDB] = reinterpret_cast<__nv_bfloat16(*)[GBK][LDB]>(sm + OFF_BH);
    __nv_bfloat16 (*BsL)[GBK][LDB] = reinterpret_cast<__nv_bfloat16(*)[GBK][LDB]>(sm + OFF_BL);
    float (*Cs)[LDC] = reinterpret_cast<float(*)[LDC]>(sm);
    float* bias = reinterpret_cast<float*>(sm + OFF_BIAS);

    const int tid = threadIdx.x;
    const int wid = tid >> 5;
    const int wm = wid & 3;           // 0..3 : M warp coord (32-row tile)
    const int wn = wid >> 2;          // 0..1 : N warp coord (32-col tile)
    const int m_tile = blockIdx.x * GBM;
    const int n_tile = blockIdx.y * GBN;
    const int z = blockIdx.z;

    const __nv_bfloat16* __restrict__ XH = z ? g_xb_hi : g_xa_hi;
    const __nv_bfloat16* __restrict__ XL = z ? g_xb_lo : g_xa_lo;
    const __nv_bfloat16* __restrict__ WH = g_w_hi + (size_t)z * Dd * Hh;
    const __nv_bfloat16* __restrict__ WL = g_w_lo + (size_t)z * Dd * Hh;
    float* __restrict__ Cg = z ? g_hb : g_ha;

    if (tid < GBN)
        bias[tid] = z ? 0.f : b1[n_tile + tid];

    // global-load mapping (uint4 = 8 bf16)
    // A: 512 uint4 per variant; thread covers t=tid and t=tid+256
    const int ar0 = tid >> 2;                // rows 0..63
    const int ar1 = (tid + 256) >> 2;        // rows 64..127
    const int ac  = (tid & 3) * 8;
    // B: 256 uint4 per variant (32 rows x 64 cols)
    const int br = tid >> 3;                 // 0..31 (k row)
    const int bc = (tid & 7) * 8;            // 0..56 (n col)

    const __nv_bfloat16* XHp0 = XH + (size_t)(m_tile + ar0) * Dd + ac;
    const __nv_bfloat16* XHp1 = XH + (size_t)(m_tile + ar1) * Dd + ac;
    const __nv_bfloat16* XLp0 = XL + (size_t)(m_tile + ar0) * Dd + ac;
    const __nv_bfloat16* XLp1 = XL + (size_t)(m_tile + ar1) * Dd + ac;
    const __nv_bfloat16* WHp  = WH + (size_t)br * Hh + n_tile + bc;
    const __nv_bfloat16* WLp  = WL + (size_t)br * Hh + n_tile + bc;

    // stage k-block 0
    {
        *reinterpret_cast<uint4*>(&AsH[0][ar0][ac]) = *reinterpret_cast<const uint4*>(XHp0);
        *reinterpret_cast<uint4*>(&AsH[0][ar1][ac]) = *reinterpret_cast<const uint4*>(XHp1);
        *reinterpret_cast<uint4*>(&AsL[0][ar0][ac]) = *reinterpret_cast<const uint4*>(XLp0);
        *reinterpret_cast<uint4*>(&AsL[0][ar1][ac]) = *reinterpret_cast<const uint4*>(XLp1);
        *reinterpret_cast<uint4*>(&BsH[0][br][bc])  = *reinterpret_cast<const uint4*>(WHp);
        *reinterpret_cast<uint4*>(&BsL[0][br][bc])  = *reinterpret_cast<const uint4*>(WLp);
    }
    __syncthreads();

    wmma::fragment<wmma::accumulator, 16, 16, 16, float> acc[2][2];
    #pragma unroll
    for (int i = 0; i < 2; i++)
        #pragma unroll
        for (int j = 0; j < 2; j++)
            wmma::fill_fragment(acc[i][j], 0.f);

    uint4 pah0, pah1, pal0, pal1, pbh, pbl;
    for (int kb = 0; kb < NKB; kb++) {
        const int cur = kb & 1;
        if (kb + 1 < NKB) {
            const int ko = (kb + 1) * GBK;
            pah0 = *reinterpret_cast<const uint4*>(XHp0 + ko);
            pah1 = *reinterpret_cast<const uint4*>(XHp1 + ko);
            pal0 = *reinterpret_cast<const uint4*>(XLp0 + ko);
            pal1 = *reinterpret_cast<const uint4*>(XLp1 + ko);
            pbh  = *reinterpret_cast<const uint4*>(WHp + (size_t)ko * Hh);
            pbl  = *reinterpret_cast<const uint4*>(WLp + (size_t)ko * Hh);
        }

        #pragma unroll
        for (int ks = 0; ks < GBK; ks += 16) {
            wmma::fragment<wmma::matrix_a, 16, 16, 16, __nv_bfloat16,
                           wmma::row_major> afH[2], afL[2];
            wmma::fragment<wmma::matrix_b, 16, 16, 16, __nv_bfloat16,
                           wmma::row_major> bfH[2], bfL[2];
            #pragma unroll
            for (int i = 0; i < 2; i++) {
                wmma::load_matrix_sync(afH[i], &AsH[cur][wm * 32 + 16 * i][ks], LDA);
                wmma::load_matrix_sync(afL[i], &AsL[cur][wm * 32 + 16 * i][ks], LDA);
            }
            #pragma unroll
            for (int j = 0; j < 2; j++) {
                wmma::load_matrix_sync(bfH[j], &BsH[cur][ks][wn * 32 + 16 * j], LDB);
                wmma::load_matrix_sync(bfL[j], &BsL[cur][ks][wn * 32 + 16 * j], LDB);
            }
            #pragma unroll
            for (int i = 0; i < 2; i++)
                #pragma unroll
                for (int j = 0; j < 2; j++) {
                    wmma::mma_sync(acc[i][j], afH[i], bfH[j], acc[i][j]);
                    wmma::mma_sync(acc[i][j], afL[i], bfH[j], acc[i][j]);
                    wmma::mma_sync(acc[i][j], afH[i], bfL[j], acc[i][j]);
                }
        }

        if (kb + 1 < NKB) {
            const int nxt = cur ^ 1;
            *reinterpret_cast<uint4*>(&AsH[nxt][ar0][ac]) = pah0;
            *reinterpret_cast<uint4*>(&AsH[nxt][ar1][ac]) = pah1;
            *reinterpret_cast<uint4*>(&AsL[nxt][ar0][ac]) = pal0;
            *reinterpret_cast<uint4*>(&AsL[nxt][ar1][ac]) = pal1;
            *reinterpret_cast<uint4*>(&BsH[nxt][br][bc])  = pbh;
            *reinterpret_cast<uint4*>(&BsL[nxt][br][bc])  = pbl;
        }
        __syncthreads();
    }

    // epilogue: stage C through smem (aliases tiles; safe after final sync)
    #pragma unroll
    for (int i = 0; i < 2; i++)
        #pragma unroll
        for (int j = 0; j < 2; j++)
            wmma::store_matrix_sync(&Cs[wm * 32 + 16 * i][wn * 32 + 16 * j],
                                    acc[i][j], LDC, wmma::mem_row_major);
    __syncthreads();

    // biased coalesced write: 128 rows x 16 float4
    for (int t = tid; t < GBM * (GBN / 4); t += 256) {
        int r  = t >> 4;
        int c4 = (t & 15) * 4;
        float4 v = *reinterpret_cast<const float4*>(&Cs[r][c4]);
        v.x += bias[c4];
        v.y += bias[c4 + 1];
        v.z += bias[c4 + 2];
        v.w += bias[c4 + 3];
        *reinterpret_cast<float4*>(
            Cg + (size_t)(m_tile + r) * Hh + n_tile + c4) = v;
    }
}

// ---------------------------------------------------------------------------
// pair_kernel — UNCHANGED known-good version (18.4-18.7us measured):
// out[b,i,j,:] = relu(ha[b,i,:] + hb[b,j,:]) @ W2 + b2
// ---------------------------------------------------------------------------
#define TI 16
#define TJ 32
#define HC 128
#define PP 132

__global__ __launch_bounds__(256) void pair_kernel(
    const float* __restrict__ W2, const float* __restrict__ b2,
    float2* __restrict__ out)
{
    __shared__ float sha[TI][PP];
    __shared__ float shb[TJ][PP];
    __shared__ u64   sw2[HC];      // packed (W2[h,0], W2[h,1])

    const int tid = threadIdx.x;
    const int bi = blockIdx.x, bj = blockIdx.y, bb = blockIdx.z;

    const int li = tid >> 4;   // 0..15 : i within tile
    const int lj = tid & 15;   // j and j+16 within tile

    const float* haBase = g_ha + (size_t)(bb * Ss + bi * TI) * Hh;
    const float* hbBase = g_hb + (size_t)(bb * Ss + bj * TJ) * Hh;

    u64 accA = 0, accB = 0;

    float4 va[2], vb[4], vw;
    {
        #pragma unroll
        for (int r = 0; r < 2; r++) {
            int idx = r * 256 + tid;
            va[r] = *reinterpret_cast<const float4*>(
                haBase + (size_t)(idx >> 5) * Hh + ((idx & 31) << 2));
        }
        #pragma unroll
        for (int r = 0; r < 4; r++) {
            int idx = r * 256 + tid;
            vb[r] = *reinterpret_cast<const float4*>(
                hbBase + (size_t)(idx >> 5) * Hh + ((idx & 31) << 2));
        }
        if (tid < 64) vw = *reinterpret_cast<const float4*>(W2 + tid * 4);
    }

    for (int h0 = 0; h0 < Hh; h0 += HC) {
        __syncthreads();
        #pragma unroll
        for (int r = 0; r < 2; r++) {
            int idx = r * 256 + tid;
            *reinterpret_cast<float4*>(&sha[idx >> 5][(idx & 31) << 2]) = va[r];
        }
        #pragma unroll
        for (int r = 0; r < 4; r++) {
            int idx = r * 256 + tid;
            *reinterpret_cast<float4*>(&shb[idx >> 5][(idx & 31) << 2]) = vb[r];
        }
        if (tid < 64) *reinterpret_cast<float4*>(&sw2[tid * 2]) = vw;
        __syncthreads();

        if (h0 + HC < Hh) {
            int hn = h0 + HC;
            #pragma unroll
            for (int r = 0; r < 2; r++) {
                int idx = r * 256 + tid;
                va[r] = *reinterpret_cast<const float4*>(
                    haBase + (size_t)(idx >> 5) * Hh + hn + ((idx & 31) << 2));
            }
            #pragma unroll
            for (int r = 0; r < 4; r++) {
                int idx = r * 256 + tid;
                vb[r] = *reinterpret_cast<const float4*>(
                    hbBase + (size_t)(idx >> 5) * Hh + hn + ((idx & 31) << 2));
            }
            if (tid < 64) vw = *reinterpret_cast<const float4*>(W2 + 2 * hn + tid * 4);
        }

        #pragma unroll 8
        for (int c = 0; c < HC; c += 4) {
            float4 xa  = *reinterpret_cast<const float4*>(&sha[li][c]);
            float4 xb0 = *reinterpret_cast<const float4*>(&shb[lj][c]);
            float4 xb1 = *reinterpret_cast<const float4*>(&shb[lj + 16][c]);
            u64 w0 = sw2[c], w1 = sw2[c + 1], w2v = sw2[c + 2], w3 = sw2[c + 3];
            float sA, sB;
            sA = fmaxf(xa.x + xb0.x, 0.f); sB = fmaxf(xa.x + xb1.x, 0.f);
            fma2(accA, pk_dup(sA), w0);    fma2(accB, pk_dup(sB), w0);
            sA = fmaxf(xa.y + xb0.y, 0.f); sB = fmaxf(xa.y + xb1.y, 0.f);
            fma2(accA, pk_dup(sA), w1);    fma2(accB, pk_dup(sB), w1);
            sA = fmaxf(xa.z + xb0.z, 0.f); sB = fmaxf(xa.z + xb1.z, 0.f);
            fma2(accA, pk_dup(sA), w2v);   fma2(accB, pk_dup(sB), w2v);
            sA = fmaxf(xa.w + xb0.w, 0.f); sB = fmaxf(xa.w + xb1.w, 0.f);
            fma2(accA, pk_dup(sA), w3);    fma2(accB, pk_dup(sB), w3);
        }
    }

    float aAl, aAh, aBl, aBh;
    upk(accA, aAl, aAh);
    upk(accB, aBl, aBh);
    const float b20 = b2[0], b21 = b2[1];

    size_t base = ((size_t)bb * Ss + bi * TI + li) * Ss + bj * TJ + lj;
    out[base]      = make_float2(aAl + b20, aAh + b21);
    out[base + 16] = make_float2(aBl + b20, aBh + b21);
}

// ---------------------------------------------------------------------------
// launch
// ---------------------------------------------------------------------------
extern "C" void kernel_launch(void* const* d_in, const int* in_sizes, int n_in,
                              void* d_out, int out_size)
{
    // Input mapping by element count:
    // a,b: 393216 ; W1: 1179648 ; b1: 768 ; W2: 1536 ; b2: 2
    const float *a = nullptr, *b = nullptr, *W1 = nullptr, *b1 = nullptr,
                *W2 = nullptr, *b2 = nullptr;
    for (int i = 0; i < n_in; i++) {
        const float* p = (const float*)d_in[i];
        switch (in_sizes[i]) {
            case NA:          if (!a) a = p; else b = p; break;  // a first, then b
            case NW:          W1 = p; break;
            case Hh:          b1 = p; break;
            case Hh * 2:      W2 = p; break;
            case 2:           b2 = p; break;
            default: break;
        }
    }

    cudaFuncSetAttribute(gemm_kernel,
                         cudaFuncAttributeMaxDynamicSharedMemorySize, SM_TOT);

    split_kernel<<<(2 * NA + NW) / 1024, 256>>>(a, b, W1);
    gemm_kernel<<<dim3(MT / GBM, Hh / GBN, 2), 256, SM_TOT>>>(b1);
    pair_kernel<<<dim3(Ss / TI, Ss / TJ, Bb), 256>>>(W2, b2, (float2*)d_out);

    (void)out_size;
}